// round 11
// baseline (speedup 1.0000x reference)
#include <cuda_runtime.h>
#include <cuda_fp16.h>
#include <cstdint>

// ============================ problem constants ============================
#define IN_DIM   4096
#define OUT_DIM  11008
#define BATCH    64
#define GROUP    128
#define BK       128                 // K per mainloop iteration == GROUP
#define KSPLIT   5                   // uneven splits {7,7,6,6,6}
#define NKB_TOT  (IN_DIM / BK)       // 32 k-blocks total
#define CTA_N    128                 // output channels per CTA
#define NTILES   (OUT_DIM / CTA_N)   // 86
#define NCTA     (NTILES * KSPLIT)   // 430
#define NTHREADS 256                 // 8 warps: 2 (M=batch) x 4 (N=channels)

// ---- SMEM stage layout (bytes, relative to stage base) ----
#define A_BYTES   16384              // x tile: 64 rows x 256B
#define W_BYTES   8192               // qweight tile: 16 rows x 512B
#define S_OFF     (A_BYTES + W_BYTES)          // 24576
#define Z_OFF     (S_OFF + 512)                 // 25088
#define STAGE     25600
#define NSTAGE    2
#define SMEM_ALLOC (NSTAGE * STAGE + 1024)      // 52224; x3 CTAs = 156672 <= 228KB

// x pre-converted to fp16 with intra-8 k-permutation [0,4,1,5,2,6,3,7]
__device__ __align__(16) __half g_xperm[BATCH * IN_DIM];

// ============================ helpers ============================
__device__ __forceinline__ uint32_t smem_u32(const void* p) {
    uint32_t a;
    asm("{ .reg .u64 t; cvta.to.shared.u64 t, %1; cvt.u32.u64 %0, t; }" : "=r"(a) : "l"(p));
    return a;
}

// magic dequant: nibbles (j, j+4) of q (j = sh/4) -> fp16x2 (v - z) * s.
__device__ __forceinline__ uint32_t dq_pair(uint32_t q, int sh, __half2 s2, __half2 b2) {
    uint32_t p = ((q >> sh) & 0x000F000Fu) | 0x64006400u;
    __half2 hv = *reinterpret_cast<__half2*>(&p);
    const __half2 c1024 = __half2half2(__ushort_as_half((unsigned short)0x6400u));
    __half2 w = __hfma2(__hsub2(hv, c1024), s2, b2);   // (v - z) * s
    return *reinterpret_cast<uint32_t*>(&w);
}

__device__ __forceinline__ void mma16816(float* c, const uint32_t* a, uint32_t b0, uint32_t b1) {
    asm volatile(
        "mma.sync.aligned.m16n8k16.row.col.f32.f16.f16.f32 "
        "{%0,%1,%2,%3}, {%4,%5,%6,%7}, {%8,%9}, {%0,%1,%2,%3};"
        : "+f"(c[0]), "+f"(c[1]), "+f"(c[2]), "+f"(c[3])
        : "r"(a[0]), "r"(a[1]), "r"(a[2]), "r"(a[3]), "r"(b0), "r"(b1));
}

__device__ __forceinline__ void ldmatrix_x4(uint32_t* r, uint32_t addr) {
    asm volatile("ldmatrix.sync.aligned.m8n8.x4.shared.b16 {%0,%1,%2,%3}, [%4];"
                 : "=r"(r[0]), "=r"(r[1]), "=r"(r[2]), "=r"(r[3]) : "r"(addr));
}

__device__ __forceinline__ void cp_async16(uint32_t dst, const void* src) {
    asm volatile("cp.async.cg.shared.global [%0], [%1], 16;" :: "r"(dst), "l"(src));
}
#define CP_COMMIT() asm volatile("cp.async.commit_group;" ::: "memory")
#define CP_WAIT(n)  asm volatile("cp.async.wait_group %0;" :: "n"(n) : "memory")

// fire-and-forget global float add (REDG)
__device__ __forceinline__ void redg_add(float* p, float v) {
    asm volatile("red.global.add.f32 [%0], %1;" :: "l"(p), "f"(v) : "memory");
}

// ============================ x pre-permute + out-zero kernel ============================
// grid covers BATCH*OUT_DIM/4 threads: each zeroes ONE float4 of out;
// the first BATCH*IN_DIM/8 threads also convert one 8-float chunk of x.
__global__ void __launch_bounds__(256) xperm_kernel(const float* __restrict__ x,
                                                    float* __restrict__ out) {
    int idx = blockIdx.x * blockDim.x + threadIdx.x;
    if (idx < BATCH * IN_DIM / 8) {
        const float4* p = reinterpret_cast<const float4*>(x) + (size_t)idx * 2;
        float4 a = p[0], b = p[1];
        __half2 h0 = __floats2half2_rn(a.x, b.x);
        __half2 h1 = __floats2half2_rn(a.y, b.y);
        __half2 h2 = __floats2half2_rn(a.z, b.z);
        __half2 h3 = __floats2half2_rn(a.w, b.w);
        uint4 o;
        o.x = *reinterpret_cast<uint32_t*>(&h0);
        o.y = *reinterpret_cast<uint32_t*>(&h1);
        o.z = *reinterpret_cast<uint32_t*>(&h2);
        o.w = *reinterpret_cast<uint32_t*>(&h3);
        reinterpret_cast<uint4*>(g_xperm)[idx] = o;
    }
    if (idx < BATCH * OUT_DIM / 4)
        reinterpret_cast<float4*>(out)[idx] = make_float4(0.f, 0.f, 0.f, 0.f);
}

// ============================ main kernel ============================
// Grid: 430 CTAs = 86 n-tiles x 5 k-splits (uneven {7,7,6,6,6} k-blocks).
// Warp grid 2(M) x 4(N): warp (mw,nw) computes batch rows [32mw,+32) x
// channels [32nw,+32). Register-direct dequant (no W16 staging).
// 2-stage cp.async pipeline, one barrier per iteration, REDG epilogue.
__global__ void __launch_bounds__(NTHREADS, 3)
mpq_kernel(const uint32_t* __restrict__ qweight,
           const float* __restrict__ scales,
           const float* __restrict__ zeros,
           float* __restrict__ out) {
    extern __shared__ __align__(128) uint8_t smraw[];
    uint8_t* sm = (uint8_t*)(((uintptr_t)smraw + 1023u) & ~(uintptr_t)1023u);
    const uint32_t sbase = smem_u32(sm);

    const int t     = threadIdx.x;
    const int lane  = t & 31;
    const int wid   = t >> 5;
    const int mw    = wid >> 2;        // 0..1: batch-row group (32 rows)
    const int nw    = wid & 3;         // 0..3: channel group (32 channels)
    const int kc    = lane & 3;        // k-pair selector within k16
    const int nl    = lane >> 2;       // n within 8-wide n-tile
    const int ntile = blockIdx.x % NTILES;
    const int split = blockIdx.x / NTILES;
    const int nbase = ntile * CTA_N;
    const int kb0   = split * 6 + (split < 2 ? split : 2);  // {0,7,14,20,26}
    const int nkb   = 6 + (split < 2 ? 1 : 0);              // {7,7,6,6,6}

    // ---- stage loader (pure cp.async) ----
    auto load_stage = [&](int stage, int kbg) {
        uint32_t stb = sbase + stage * STAGE;
        // A: x tile, 64 rows x 256B, XOR-swizzled in 16B chunks
        {
            int row = t >> 2;
            int cg  = t & 3;
            const __half* src = g_xperm + (size_t)row * IN_DIM + kbg * BK;
            uint32_t dst_row = stb + row * 256;
            int rx = row & 7;
#pragma unroll
            for (int i = 0; i < 4; i++) {
                int c = cg * 4 + i;
                cp_async16(dst_row + (uint32_t)((c ^ rx) * 16), src + c * 8);
            }
        }
        // W: qweight rows kbg*16..+16, channels nbase..+128 (512B/row, linear)
        {
            const uint32_t* wsrc = qweight + (size_t)(kbg * 16) * OUT_DIM + nbase;
            uint32_t dstW = stb + A_BYTES;
#pragma unroll
            for (int i = 0; i < 2; i++) {
                int id = t * 2 + i;          // 0..511
                int r = id >> 5, c = id & 31;
                cp_async16(dstW + (uint32_t)id * 16, wsrc + (size_t)r * OUT_DIM + c * 4);
            }
        }
        // S/Z: 128 floats each
        if (t < 32) {
            cp_async16(stb + S_OFF + t * 16, scales + (size_t)kbg * OUT_DIM + nbase + t * 4);
        } else if (t < 64) {
            int u = t - 32;
            cp_async16(stb + Z_OFF + u * 16, zeros + (size_t)kbg * OUT_DIM + nbase + u * 4);
        }
    };

    float acc[4][2][4];                // [n-tile][m-tile][frag]
#pragma unroll
    for (int nt = 0; nt < 4; nt++)
#pragma unroll
        for (int mt = 0; mt < 2; mt++)
#pragma unroll
            for (int i = 0; i < 4; i++) acc[nt][mt][i] = 0.f;

    const int lm_m  = lane & 15;    // row within m16 tile
    const int lm_kh = lane >> 4;    // k-half (0/1)
    const int lm_x  = lane & 7;     // row XOR key

    load_stage(0, kb0);
    CP_COMMIT();

#pragma unroll 1
    for (int kb = 0; kb < nkb; kb++) {
        const int s = kb & 1;
        CP_WAIT(0);          // only load(kb) outstanding -> wait for it
        __syncthreads();     // data visible to all warps; stage s^1 free
        if (kb + 1 < nkb) {
            load_stage(s ^ 1, kb0 + kb + 1);   // hidden behind this kb's compute
            CP_COMMIT();
        }

        const uint8_t*  stb  = sm + s * STAGE;
        const uint32_t  ab   = sbase + s * STAGE;
        const uint32_t* smW  = (const uint32_t*)(stb + A_BYTES);
        const float*    smS  = (const float*)(stb + S_OFF);
        const float*    smZ  = (const float*)(stb + Z_OFF);

        __half2 S2[4], B2[4];
#pragma unroll
        for (int nt = 0; nt < 4; nt++) {
            int nloc = nw * 32 + nt * 8 + nl;
            float sc = smS[nloc];
            float zr = smZ[nloc];
            S2[nt] = __float2half2_rn(sc);
            B2[nt] = __float2half2_rn(-zr * sc);
        }

#pragma unroll
        for (int s16 = 0; s16 < 8; s16++) {
            // A fragments: 2 m-tiles of this warp's 32 batch rows
            uint32_t a[2][4];
#pragma unroll
            for (int mt = 0; mt < 2; mt++) {
                int m = mw * 32 + mt * 16 + lm_m;
                uint32_t addr = ab + (uint32_t)(m * 256)
                              + (uint32_t)(((2 * s16 + lm_kh) ^ (m & 7)) * 16);
                ldmatrix_x4(a[mt], addr);
            }
            // B fragments: dequant 4 n-tiles from packed SMEM
#pragma unroll
            for (int nt = 0; nt < 4; nt++) {
                int nloc = nw * 32 + nt * 8 + nl;
                uint32_t qlo = smW[(2 * s16)     * CTA_N + nloc];
                uint32_t qhi = smW[(2 * s16 + 1) * CTA_N + nloc];
                uint32_t b0 = dq_pair(qlo, 4 * kc, S2[nt], B2[nt]);
                uint32_t b1 = dq_pair(qhi, 4 * kc, S2[nt], B2[nt]);
                mma16816(acc[nt][0], a[0], b0, b1);
                mma16816(acc[nt][1], a[1], b0, b1);
            }
        }
    }

    // ---- epilogue: accumulate into out via fire-and-forget global adds ----
#pragma unroll
    for (int nt = 0; nt < 4; nt++) {
        int n = nbase + nw * 32 + nt * 8 + (lane & 3) * 2;
#pragma unroll
        for (int mt = 0; mt < 2; mt++) {
            int m = mw * 32 + mt * 16 + (lane >> 2);
            float* p0 = out + (size_t)m * OUT_DIM + n;
            float* p1 = out + (size_t)(m + 8) * OUT_DIM + n;
            redg_add(p0,     acc[nt][mt][0]);
            redg_add(p0 + 1, acc[nt][mt][1]);
            redg_add(p1,     acc[nt][mt][2]);
            redg_add(p1 + 1, acc[nt][mt][3]);
        }
    }
}

// ============================ launch ============================
extern "C" void kernel_launch(void* const* d_in, const int* in_sizes, int n_in,
                              void* d_out, int out_size) {
    (void)in_sizes; (void)n_in; (void)out_size;
    const float*    x       = (const float*)d_in[0];
    const uint32_t* qweight = (const uint32_t*)d_in[1];
    const float*    scales  = (const float*)d_in[2];
    const float*    zeros   = (const float*)d_in[3];
    // d_in[4] = g_idx (unused: g_idx[i] == i / GROUP by construction)
    float* out = (float*)d_out;

    xperm_kernel<<<(BATCH * OUT_DIM / 4 + 255) / 256, 256>>>(x, out);

    cudaFuncSetAttribute(mpq_kernel, cudaFuncAttributeMaxDynamicSharedMemorySize, SMEM_ALLOC);
    mpq_kernel<<<NCTA, NTHREADS, SMEM_ALLOC>>>(qweight, scales, zeros, out);
}

// round 12
// speedup vs baseline: 1.0071x; 1.0071x over previous
#include <cuda_runtime.h>
#include <cuda_fp16.h>
#include <cstdint>

// ============================ problem constants ============================
#define IN_DIM   4096
#define OUT_DIM  11008
#define BATCH    64
#define GROUP    128
#define BK       128                 // K per mainloop iteration == GROUP
#define KSPLIT   5                   // uneven splits {7,7,6,6,6}
#define NKB_TOT  (IN_DIM / BK)       // 32 k-blocks total
#define CTA_N    128                 // output channels per CTA
#define NTILES   (OUT_DIM / CTA_N)   // 86
#define NCTA     (NTILES * KSPLIT)   // 430
#define NTHREADS 256                 // 8 warps: 2 (M=batch) x 4 (N=channels)

// ---- SMEM stage layout (bytes, relative to stage base) ----
#define A_BYTES   16384              // x tile: 64 rows x 256B
#define W_BYTES   8192               // qweight tile: 16 rows x 512B
#define S_OFF     (A_BYTES + W_BYTES)          // 24576
#define Z_OFF     (S_OFF + 512)                 // 25088
#define STAGE     25600
#define NSTAGE    2
#define SMEM_ALLOC (NSTAGE * STAGE + 1024)      // 52224; x3 CTAs = 156672 <= 228KB

// x pre-converted to fp16 with intra-8 k-permutation [0,4,1,5,2,6,3,7]
__device__ __align__(16) __half g_xperm[BATCH * IN_DIM];

// ============================ helpers ============================
__device__ __forceinline__ uint32_t smem_u32(const void* p) {
    uint32_t a;
    asm("{ .reg .u64 t; cvta.to.shared.u64 t, %1; cvt.u32.u64 %0, t; }" : "=r"(a) : "l"(p));
    return a;
}

// magic dequant: nibbles (j, j+4) of q (j = sh/4) -> fp16x2 (v - z) * s.
__device__ __forceinline__ uint32_t dq_pair(uint32_t q, int sh, __half2 s2, __half2 b2) {
    uint32_t p = ((q >> sh) & 0x000F000Fu) | 0x64006400u;
    __half2 hv = *reinterpret_cast<__half2*>(&p);
    const __half2 c1024 = __half2half2(__ushort_as_half((unsigned short)0x6400u));
    __half2 w = __hfma2(__hsub2(hv, c1024), s2, b2);   // (v - z) * s
    return *reinterpret_cast<uint32_t*>(&w);
}

__device__ __forceinline__ void mma16816(float* c, const uint32_t* a, uint32_t b0, uint32_t b1) {
    asm volatile(
        "mma.sync.aligned.m16n8k16.row.col.f32.f16.f16.f32 "
        "{%0,%1,%2,%3}, {%4,%5,%6,%7}, {%8,%9}, {%0,%1,%2,%3};"
        : "+f"(c[0]), "+f"(c[1]), "+f"(c[2]), "+f"(c[3])
        : "r"(a[0]), "r"(a[1]), "r"(a[2]), "r"(a[3]), "r"(b0), "r"(b1));
}

__device__ __forceinline__ void ldmatrix_x4(uint32_t* r, uint32_t addr) {
    asm volatile("ldmatrix.sync.aligned.m8n8.x4.shared.b16 {%0,%1,%2,%3}, [%4];"
                 : "=r"(r[0]), "=r"(r[1]), "=r"(r[2]), "=r"(r[3]) : "r"(addr));
}

__device__ __forceinline__ void cp_async16(uint32_t dst, const void* src) {
    asm volatile("cp.async.cg.shared.global [%0], [%1], 16;" :: "r"(dst), "l"(src));
}
#define CP_COMMIT() asm volatile("cp.async.commit_group;" ::: "memory")
#define CP_WAIT(n)  asm volatile("cp.async.wait_group %0;" :: "n"(n) : "memory")

// fire-and-forget global float add (REDG)
__device__ __forceinline__ void redg_add(float* p, float v) {
    asm volatile("red.global.add.f32 [%0], %1;" :: "l"(p), "f"(v) : "memory");
}

// ============================ x pre-permute + out-zero kernel ============================
// grid covers BATCH*OUT_DIM/4 threads: each zeroes ONE float4 of out;
// the first BATCH*IN_DIM/8 threads also convert one 8-float chunk of x.
__global__ void __launch_bounds__(256) xperm_kernel(const float* __restrict__ x,
                                                    float* __restrict__ out) {
    int idx = blockIdx.x * blockDim.x + threadIdx.x;
    if (idx < BATCH * IN_DIM / 8) {
        const float4* p = reinterpret_cast<const float4*>(x) + (size_t)idx * 2;
        float4 a = p[0], b = p[1];
        __half2 h0 = __floats2half2_rn(a.x, b.x);
        __half2 h1 = __floats2half2_rn(a.y, b.y);
        __half2 h2 = __floats2half2_rn(a.z, b.z);
        __half2 h3 = __floats2half2_rn(a.w, b.w);
        uint4 o;
        o.x = *reinterpret_cast<uint32_t*>(&h0);
        o.y = *reinterpret_cast<uint32_t*>(&h1);
        o.z = *reinterpret_cast<uint32_t*>(&h2);
        o.w = *reinterpret_cast<uint32_t*>(&h3);
        reinterpret_cast<uint4*>(g_xperm)[idx] = o;
    }
    if (idx < BATCH * OUT_DIM / 4)
        reinterpret_cast<float4*>(out)[idx] = make_float4(0.f, 0.f, 0.f, 0.f);
}

// ============================ main kernel ============================
// Grid: 430 CTAs = 86 n-tiles x 5 k-splits (uneven {7,7,6,6,6} k-blocks).
// Warp grid 2(M) x 4(N): warp (mw,nw) computes batch rows [32mw,+32) x
// channels [32nw,+32). Register-direct dequant (no W16 staging).
// 2-stage cp.async pipeline, one barrier per iteration, REDG epilogue.
__global__ void __launch_bounds__(NTHREADS, 3)
mpq_kernel(const uint32_t* __restrict__ qweight,
           const float* __restrict__ scales,
           const float* __restrict__ zeros,
           float* __restrict__ out) {
    extern __shared__ __align__(128) uint8_t smraw[];
    uint8_t* sm = (uint8_t*)(((uintptr_t)smraw + 1023u) & ~(uintptr_t)1023u);
    const uint32_t sbase = smem_u32(sm);

    const int t     = threadIdx.x;
    const int lane  = t & 31;
    const int wid   = t >> 5;
    const int mw    = wid >> 2;        // 0..1: batch-row group (32 rows)
    const int nw    = wid & 3;         // 0..3: channel group (32 channels)
    const int kc    = lane & 3;        // k-pair selector within k16
    const int nl    = lane >> 2;       // n within 8-wide n-tile
    const int ntile = blockIdx.x % NTILES;
    const int split = blockIdx.x / NTILES;
    const int nbase = ntile * CTA_N;
    const int kb0   = split * 6 + (split < 2 ? split : 2);  // {0,7,14,20,26}
    const int nkb   = 6 + (split < 2 ? 1 : 0);              // {7,7,6,6,6}

    // ---- stage loader (pure cp.async) ----
    auto load_stage = [&](int stage, int kbg) {
        uint32_t stb = sbase + stage * STAGE;
        // A: x tile, 64 rows x 256B, XOR-swizzled in 16B chunks
        {
            int row = t >> 2;
            int cg  = t & 3;
            const __half* src = g_xperm + (size_t)row * IN_DIM + kbg * BK;
            uint32_t dst_row = stb + row * 256;
            int rx = row & 7;
#pragma unroll
            for (int i = 0; i < 4; i++) {
                int c = cg * 4 + i;
                cp_async16(dst_row + (uint32_t)((c ^ rx) * 16), src + c * 8);
            }
        }
        // W: qweight rows kbg*16..+16, channels nbase..+128 (512B/row, linear)
        {
            const uint32_t* wsrc = qweight + (size_t)(kbg * 16) * OUT_DIM + nbase;
            uint32_t dstW = stb + A_BYTES;
#pragma unroll
            for (int i = 0; i < 2; i++) {
                int id = t * 2 + i;          // 0..511
                int r = id >> 5, c = id & 31;
                cp_async16(dstW + (uint32_t)id * 16, wsrc + (size_t)r * OUT_DIM + c * 4);
            }
        }
        // S/Z: 128 floats each
        if (t < 32) {
            cp_async16(stb + S_OFF + t * 16, scales + (size_t)kbg * OUT_DIM + nbase + t * 4);
        } else if (t < 64) {
            int u = t - 32;
            cp_async16(stb + Z_OFF + u * 16, zeros + (size_t)kbg * OUT_DIM + nbase + u * 4);
        }
    };

    float acc[4][2][4];                // [n-tile][m-tile][frag]
#pragma unroll
    for (int nt = 0; nt < 4; nt++)
#pragma unroll
        for (int mt = 0; mt < 2; mt++)
#pragma unroll
            for (int i = 0; i < 4; i++) acc[nt][mt][i] = 0.f;

    const int lm_m  = lane & 15;    // row within m16 tile
    const int lm_kh = lane >> 4;    // k-half (0/1)
    const int lm_x  = lane & 7;     // row XOR key

    load_stage(0, kb0);
    CP_COMMIT();

#pragma unroll 1
    for (int kb = 0; kb < nkb; kb++) {
        const int s = kb & 1;
        CP_WAIT(0);          // only load(kb) outstanding -> wait for it
        __syncthreads();     // data visible to all warps; stage s^1 free
        if (kb + 1 < nkb) {
            load_stage(s ^ 1, kb0 + kb + 1);   // hidden behind this kb's compute
            CP_COMMIT();
        }

        const uint8_t*  stb  = sm + s * STAGE;
        const uint32_t  ab   = sbase + s * STAGE;
        const uint32_t* smW  = (const uint32_t*)(stb + A_BYTES);
        const float*    smS  = (const float*)(stb + S_OFF);
        const float*    smZ  = (const float*)(stb + Z_OFF);

        __half2 S2[4], B2[4];
#pragma unroll
        for (int nt = 0; nt < 4; nt++) {
            int nloc = nw * 32 + nt * 8 + nl;
            float sc = smS[nloc];
            float zr = smZ[nloc];
            S2[nt] = __float2half2_rn(sc);
            B2[nt] = __float2half2_rn(-zr * sc);
        }

#pragma unroll
        for (int s16 = 0; s16 < 8; s16++) {
            // A fragments: 2 m-tiles of this warp's 32 batch rows
            uint32_t a[2][4];
#pragma unroll
            for (int mt = 0; mt < 2; mt++) {
                int m = mw * 32 + mt * 16 + lm_m;
                uint32_t addr = ab + (uint32_t)(m * 256)
                              + (uint32_t)(((2 * s16 + lm_kh) ^ (m & 7)) * 16);
                ldmatrix_x4(a[mt], addr);
            }
            // B fragments: dequant 4 n-tiles from packed SMEM
#pragma unroll
            for (int nt = 0; nt < 4; nt++) {
                int nloc = nw * 32 + nt * 8 + nl;
                uint32_t qlo = smW[(2 * s16)     * CTA_N + nloc];
                uint32_t qhi = smW[(2 * s16 + 1) * CTA_N + nloc];
                uint32_t b0 = dq_pair(qlo, 4 * kc, S2[nt], B2[nt]);
                uint32_t b1 = dq_pair(qhi, 4 * kc, S2[nt], B2[nt]);
                mma16816(acc[nt][0], a[0], b0, b1);
                mma16816(acc[nt][1], a[1], b0, b1);
            }
        }
    }

    // ---- epilogue: accumulate into out via fire-and-forget global adds ----
#pragma unroll
    for (int nt = 0; nt < 4; nt++) {
        int n = nbase + nw * 32 + nt * 8 + (lane & 3) * 2;
#pragma unroll
        for (int mt = 0; mt < 2; mt++) {
            int m = mw * 32 + mt * 16 + (lane >> 2);
            float* p0 = out + (size_t)m * OUT_DIM + n;
            float* p1 = out + (size_t)(m + 8) * OUT_DIM + n;
            redg_add(p0,     acc[nt][mt][0]);
            redg_add(p0 + 1, acc[nt][mt][1]);
            redg_add(p1,     acc[nt][mt][2]);
            redg_add(p1 + 1, acc[nt][mt][3]);
        }
    }
}

// ============================ launch ============================
extern "C" void kernel_launch(void* const* d_in, const int* in_sizes, int n_in,
                              void* d_out, int out_size) {
    (void)in_sizes; (void)n_in; (void)out_size;
    const float*    x       = (const float*)d_in[0];
    const uint32_t* qweight = (const uint32_t*)d_in[1];
    const float*    scales  = (const float*)d_in[2];
    const float*    zeros   = (const float*)d_in[3];
    // d_in[4] = g_idx (unused: g_idx[i] == i / GROUP by construction)
    float* out = (float*)d_out;

    xperm_kernel<<<(BATCH * OUT_DIM / 4 + 255) / 256, 256>>>(x, out);

    cudaFuncSetAttribute(mpq_kernel, cudaFuncAttributeMaxDynamicSharedMemorySize, SMEM_ALLOC);
    mpq_kernel<<<NCTA, NTHREADS, SMEM_ALLOC>>>(qweight, scales, zeros, out);
}

// round 13
// speedup vs baseline: 1.0991x; 1.0914x over previous
#include <cuda_runtime.h>
#include <cuda_fp16.h>
#include <cstdint>

// ============================ problem constants ============================
#define IN_DIM   4096
#define OUT_DIM  11008
#define BATCH    64
#define GROUP    128
#define BK       128                 // K per mainloop iteration == GROUP
#define KSPLIT   5                   // uneven splits {7,7,6,6,6}
#define NKB_TOT  (IN_DIM / BK)       // 32 k-blocks total
#define CTA_N    128                 // output channels per CTA
#define NTILES   (OUT_DIM / CTA_N)   // 86
#define NCTA     (NTILES * KSPLIT)   // 430
#define NTHREADS 256                 // 8 warps, each N=16 (full M=64)
#define WARP_N   16

// ---- SMEM stage layout (bytes, relative to stage base) ----
#define A_BYTES   16384              // x tile: 64 rows x 256B
#define W_BYTES   8192               // qweight tile: 16 rows x 512B
#define SZ_OFF    (A_BYTES + W_BYTES)          // 24576: packed (s,b) u32 x 128
#define STAGE     25088              // 128-byte multiple: bank pattern preserved
#define NSTAGE    2
#define MB_OFF    (NSTAGE * STAGE)   // 50176: 4 mbarriers (full0,full1,empty0,empty1)
#define SMEM_ALLOC (MB_OFF + 64 + 1024)        // 51264; x3 CTAs = 153792 <= 228KB

// x pre-converted to fp16 with intra-8 k-permutation [0,4,1,5,2,6,3,7]
__device__ __align__(16) __half g_xperm[BATCH * IN_DIM];
// packed per-(group,channel) dequant constants: lo=half(s), hi=half(-z*s)
__device__ __align__(16) uint32_t g_szb[NKB_TOT * OUT_DIM];

// ============================ helpers ============================
__device__ __forceinline__ uint32_t smem_u32(const void* p) {
    uint32_t a;
    asm("{ .reg .u64 t; cvta.to.shared.u64 t, %1; cvt.u32.u64 %0, t; }" : "=r"(a) : "l"(p));
    return a;
}

// magic dequant: nibbles (j, j+4) of q (j = sh/4) -> fp16x2 (v - z) * s.
__device__ __forceinline__ uint32_t dq_pair(uint32_t q, int sh, __half2 s2, __half2 b2) {
    uint32_t p = ((q >> sh) & 0x000F000Fu) | 0x64006400u;
    __half2 hv = *reinterpret_cast<__half2*>(&p);
    const __half2 c1024 = __half2half2(__ushort_as_half((unsigned short)0x6400u));
    __half2 w = __hfma2(__hsub2(hv, c1024), s2, b2);   // (v - z) * s
    return *reinterpret_cast<uint32_t*>(&w);
}

__device__ __forceinline__ void mma16816(float* c, const uint32_t* a, uint32_t b0, uint32_t b1) {
    asm volatile(
        "mma.sync.aligned.m16n8k16.row.col.f32.f16.f16.f32 "
        "{%0,%1,%2,%3}, {%4,%5,%6,%7}, {%8,%9}, {%0,%1,%2,%3};"
        : "+f"(c[0]), "+f"(c[1]), "+f"(c[2]), "+f"(c[3])
        : "r"(a[0]), "r"(a[1]), "r"(a[2]), "r"(a[3]), "r"(b0), "r"(b1));
}

__device__ __forceinline__ void ldmatrix_x4(uint32_t* r, uint32_t addr) {
    asm volatile("ldmatrix.sync.aligned.m8n8.x4.shared.b16 {%0,%1,%2,%3}, [%4];"
                 : "=r"(r[0]), "=r"(r[1]), "=r"(r[2]), "=r"(r[3]) : "r"(addr));
}

__device__ __forceinline__ void cp_async16(uint32_t dst, const void* src) {
    asm volatile("cp.async.cg.shared.global [%0], [%1], 16;" :: "r"(dst), "l"(src));
}

// mbarrier ops
#define MBARRIER_INIT(mbar, cnt) \
    asm volatile("mbarrier.init.shared.b64 [%0], %1;" :: "r"((uint32_t)(mbar)), "r"((uint32_t)(cnt)) : "memory")
#define MBARRIER_ARRIVE(mbar) \
    asm volatile("mbarrier.arrive.shared.b64 _, [%0];" :: "r"((uint32_t)(mbar)) : "memory")
// this thread arrives on mbar once all its prior cp.asyncs complete
#define CP_ASYNC_ARRIVE(mbar) \
    asm volatile("cp.async.mbarrier.arrive.noinc.shared.b64 [%0];" :: "r"((uint32_t)(mbar)) : "memory")
#define MBARRIER_WAIT_PARITY(mbar_a, par_a) do {                                   \
    uint32_t _mbar = (uint32_t)(mbar_a);                                           \
    uint32_t _par  = (uint32_t)(par_a);                                            \
    uint32_t _done;                                                                \
    asm volatile("{\n\t.reg .pred p;\n\t"                                          \
        "mbarrier.try_wait.parity.shared.b64 p, [%1], %2;\n\t"                     \
        "selp.b32 %0, 1, 0, p;\n\t}" : "=r"(_done) : "r"(_mbar), "r"(_par) : "memory"); \
    if (!_done) {                                                                  \
        asm volatile("{\n\t.reg .pred P1;\n\t"                                     \
            "WAIT_LOOP_%=:\n\t"                                                    \
            "mbarrier.try_wait.parity.shared.b64 P1, [%0], %1;\n\t"                \
            "@P1 bra.uni WAIT_DONE_%=;\n\t"                                        \
            "bra.uni WAIT_LOOP_%=;\n\t"                                            \
            "WAIT_DONE_%=:\n\t}" :: "r"(_mbar), "r"(_par) : "memory");             \
    }                                                                              \
} while (0)

// fire-and-forget global float add (REDG)
__device__ __forceinline__ void redg_add(float* p, float v) {
    asm volatile("red.global.add.f32 [%0], %1;" :: "l"(p), "f"(v) : "memory");
}

// ============================ pre-kernel ============================
// idx < 32768: convert one 8-float chunk of x (k-permuted) to g_xperm.
// idx < 176128: zero one float4 of out AND pack two (s,-z*s) half pairs to g_szb.
__global__ void __launch_bounds__(256) pre_kernel(const float* __restrict__ x,
                                                  const float* __restrict__ scales,
                                                  const float* __restrict__ zeros,
                                                  float* __restrict__ out) {
    int idx = blockIdx.x * blockDim.x + threadIdx.x;
    if (idx < BATCH * IN_DIM / 8) {
        const float4* p = reinterpret_cast<const float4*>(x) + (size_t)idx * 2;
        float4 a = p[0], b = p[1];
        __half2 h0 = __floats2half2_rn(a.x, b.x);
        __half2 h1 = __floats2half2_rn(a.y, b.y);
        __half2 h2 = __floats2half2_rn(a.z, b.z);
        __half2 h3 = __floats2half2_rn(a.w, b.w);
        uint4 o;
        o.x = *reinterpret_cast<uint32_t*>(&h0);
        o.y = *reinterpret_cast<uint32_t*>(&h1);
        o.z = *reinterpret_cast<uint32_t*>(&h2);
        o.w = *reinterpret_cast<uint32_t*>(&h3);
        reinterpret_cast<uint4*>(g_xperm)[idx] = o;
    }
    if (idx < BATCH * OUT_DIM / 4) {
        reinterpret_cast<float4*>(out)[idx] = make_float4(0.f, 0.f, 0.f, 0.f);
        // two packed sz entries (flat [32][11008] layout)
        float2 s2v = reinterpret_cast<const float2*>(scales)[idx];
        float2 z2v = reinterpret_cast<const float2*>(zeros)[idx];
        uint2 o;
        o.x = (uint32_t)__half_as_ushort(__float2half_rn(s2v.x))
            | ((uint32_t)__half_as_ushort(__float2half_rn(-z2v.x * s2v.x)) << 16);
        o.y = (uint32_t)__half_as_ushort(__float2half_rn(s2v.y))
            | ((uint32_t)__half_as_ushort(__float2half_rn(-z2v.y * s2v.y)) << 16);
        reinterpret_cast<uint2*>(g_szb)[idx] = o;
    }
}

// ============================ main kernel ============================
// Grid: 430 CTAs = 86 n-tiles x 5 k-splits (uneven {7,7,6,6,6} k-blocks).
// 8 warps each own N=16 channels, full M=64. 2-stage cp.async pipeline with
// mbarrier full/empty pairs (NO __syncthreads in mainloop -> warps may skew
// by one stage, decorrelating LDSM/LSU bursts). Register-direct dequant,
// REDG epilogue.
__global__ void __launch_bounds__(NTHREADS, 3)
mpq_kernel(const uint32_t* __restrict__ qweight,
           float* __restrict__ out) {
    extern __shared__ __align__(128) uint8_t smraw[];
    uint8_t* sm = (uint8_t*)(((uintptr_t)smraw + 1023u) & ~(uintptr_t)1023u);
    const uint32_t sbase = smem_u32(sm);
    const uint32_t mb_full0  = sbase + MB_OFF;
    const uint32_t mb_full1  = sbase + MB_OFF + 8;
    const uint32_t mb_empty0 = sbase + MB_OFF + 16;
    const uint32_t mb_empty1 = sbase + MB_OFF + 24;

    const int t     = threadIdx.x;
    const int lane  = t & 31;
    const int wid   = t >> 5;
    const int kc    = lane & 3;        // k-pair selector within k16
    const int nl    = lane >> 2;       // n within 8-wide n-tile
    const int ntile = blockIdx.x % NTILES;
    const int split = blockIdx.x / NTILES;
    const int nbase = ntile * CTA_N;
    const int kb0   = split * 6 + (split < 2 ? split : 2);  // {0,7,14,20,26}
    const int nkb   = 6 + (split < 2 ? 1 : 0);              // {7,7,6,6,6}

    // ---- stage loader (pure cp.async; every thread issues >=6 loads) ----
    auto load_stage = [&](int stage, int kbg) {
        uint32_t stb = sbase + stage * STAGE;
        // A: x tile, 64 rows x 256B, XOR-swizzled in 16B chunks
        {
            int row = t >> 2;
            int cg  = t & 3;
            const __half* src = g_xperm + (size_t)row * IN_DIM + kbg * BK;
            uint32_t dst_row = stb + row * 256;
            int rx = row & 7;
#pragma unroll
            for (int i = 0; i < 4; i++) {
                int c = cg * 4 + i;
                cp_async16(dst_row + (uint32_t)((c ^ rx) * 16), src + c * 8);
            }
        }
        // W: qweight rows kbg*16..+16, channels nbase..+128 (512B/row, linear)
        {
            const uint32_t* wsrc = qweight + (size_t)(kbg * 16) * OUT_DIM + nbase;
            uint32_t dstW = stb + A_BYTES;
#pragma unroll
            for (int i = 0; i < 2; i++) {
                int id = t * 2 + i;          // 0..511
                int r = id >> 5, c = id & 31;
                cp_async16(dstW + (uint32_t)id * 16, wsrc + (size_t)r * OUT_DIM + c * 4);
            }
        }
        // SZ: 128 packed u32
        if (t < 32) {
            cp_async16(stb + SZ_OFF + t * 16, g_szb + (size_t)kbg * OUT_DIM + nbase + t * 4);
        }
    };

    // ---- mbarrier init (once) ----
    if (t == 0) {
        MBARRIER_INIT(mb_full0,  NTHREADS);
        MBARRIER_INIT(mb_full1,  NTHREADS);
        MBARRIER_INIT(mb_empty0, NTHREADS);
        MBARRIER_INIT(mb_empty1, NTHREADS);
    }
    __syncthreads();   // the only CTA-wide barrier

    float acc[2][4][4];
#pragma unroll
    for (int nt = 0; nt < 2; nt++)
#pragma unroll
        for (int mt = 0; mt < 4; mt++)
#pragma unroll
            for (int i = 0; i < 4; i++) acc[nt][mt][i] = 0.f;

    const int lm_m  = lane & 15;    // row within m16 tile
    const int lm_kh = lane >> 4;    // k-half (0/1)
    const int lm_x  = lane & 7;     // row XOR key

    // prologue: arm both stages
    load_stage(0, kb0);     CP_ASYNC_ARRIVE(mb_full0);
    load_stage(1, kb0 + 1); CP_ASYNC_ARRIVE(mb_full1);

    int pf0 = 0, pf1 = 0, pe0 = 0, pe1 = 0;

#pragma unroll 1
    for (int kb = 0; kb < nkb; kb++) {
        const int s = kb & 1;
        const uint32_t mb_full  = s ? mb_full1  : mb_full0;
        const uint32_t mb_empty = s ? mb_empty1 : mb_empty0;

        // wait for stage s data (all 256 threads' cp.asyncs landed)
        if (s) { MBARRIER_WAIT_PARITY(mb_full, pf1); pf1 ^= 1; }
        else   { MBARRIER_WAIT_PARITY(mb_full, pf0); pf0 ^= 1; }

        const uint8_t*  stb  = sm + s * STAGE;
        const uint32_t  ab   = sbase + s * STAGE;
        const uint32_t* smW  = (const uint32_t*)(stb + A_BYTES);
        const uint32_t* smSZ = (const uint32_t*)(stb + SZ_OFF);

        __half2 S2[2], B2[2];
#pragma unroll
        for (int nt = 0; nt < 2; nt++) {
            uint32_t sz = smSZ[wid * WARP_N + nt * 8 + nl];
            uint32_t s2u = __byte_perm(sz, sz, 0x1010);   // (lo, lo)
            uint32_t b2u = __byte_perm(sz, sz, 0x3232);   // (hi, hi)
            S2[nt] = *reinterpret_cast<__half2*>(&s2u);
            B2[nt] = *reinterpret_cast<__half2*>(&b2u);
        }

#pragma unroll
        for (int s16 = 0; s16 < 8; s16++) {
            uint32_t a[4][4];
#pragma unroll
            for (int mt = 0; mt < 4; mt++) {
                int m = mt * 16 + lm_m;
                uint32_t addr = ab + (uint32_t)(m * 256)
                              + (uint32_t)(((2 * s16 + lm_kh) ^ lm_x) * 16);
                ldmatrix_x4(a[mt], addr);
            }
#pragma unroll
            for (int nt = 0; nt < 2; nt++) {
                int nloc = wid * WARP_N + nt * 8 + nl;
                uint32_t qlo = smW[(2 * s16)     * CTA_N + nloc];
                uint32_t qhi = smW[(2 * s16 + 1) * CTA_N + nloc];
                uint32_t b0 = dq_pair(qlo, 4 * kc, S2[nt], B2[nt]);
                uint32_t b1 = dq_pair(qhi, 4 * kc, S2[nt], B2[nt]);
#pragma unroll
                for (int mt = 0; mt < 4; mt++)
                    mma16816(acc[nt][mt], a[mt], b0, b1);
            }
        }

        // signal: this thread done reading stage s
        MBARRIER_ARRIVE(mb_empty);

        // prefetch kb+2 into the same stage once ALL threads are done with it
        if (kb + 2 < nkb) {
            if (s) { MBARRIER_WAIT_PARITY(mb_empty, pe1); pe1 ^= 1; }
            else   { MBARRIER_WAIT_PARITY(mb_empty, pe0); pe0 ^= 1; }
            load_stage(s, kb0 + kb + 2);
            CP_ASYNC_ARRIVE(mb_full);
        }
    }

    // ---- epilogue: accumulate into out via fire-and-forget global adds ----
#pragma unroll
    for (int nt = 0; nt < 2; nt++) {
        int n = nbase + wid * WARP_N + nt * 8 + (lane & 3) * 2;
#pragma unroll
        for (int mt = 0; mt < 4; mt++) {
            int m = mt * 16 + (lane >> 2);
            float* p0 = out + (size_t)m * OUT_DIM + n;
            float* p1 = out + (size_t)(m + 8) * OUT_DIM + n;
            redg_add(p0,     acc[nt][mt][0]);
            redg_add(p0 + 1, acc[nt][mt][1]);
            redg_add(p1,     acc[nt][mt][2]);
            redg_add(p1 + 1, acc[nt][mt][3]);
        }
    }
}

// ============================ launch ============================
extern "C" void kernel_launch(void* const* d_in, const int* in_sizes, int n_in,
                              void* d_out, int out_size) {
    (void)in_sizes; (void)n_in; (void)out_size;
    const float*    x       = (const float*)d_in[0];
    const uint32_t* qweight = (const uint32_t*)d_in[1];
    const float*    scales  = (const float*)d_in[2];
    const float*    zeros   = (const float*)d_in[3];
    // d_in[4] = g_idx (unused: g_idx[i] == i / GROUP by construction)
    float* out = (float*)d_out;

    pre_kernel<<<(BATCH * OUT_DIM / 4 + 255) / 256, 256>>>(x, scales, zeros, out);

    cudaFuncSetAttribute(mpq_kernel, cudaFuncAttributeMaxDynamicSharedMemorySize, SMEM_ALLOC);
    mpq_kernel<<<NCTA, NTHREADS, SMEM_ALLOC>>>(qweight, out);
}